// round 16
// baseline (speedup 1.0000x reference)
#include <cuda_runtime.h>
#include <math.h>

#define B 32
#define N 2048
#define H 256
#define F 8
#define NH 8
#define DH 32
#define C 64
#define STEPS 3
#define NSPLIT 8
#define TN 128
#define NCHUNK 16

typedef unsigned long long ull;

__device__ float  g_U[B * H * C];
__device__ float  g_const[B * C];
__device__ float  g_scores[(size_t)B * N * C];
__device__ float2 g_part[B * NCHUNK * C];
__device__ float  g_Wpart[(size_t)B * NSPLIT * H * C];
__device__ float  g_WT[B * C * H];
__device__ float  g_ctx[F * B * H];
__device__ float  g_ho[F * B * H];
__device__ float  g_ho2[F * B * H];

__device__ __forceinline__ ull pack2(float x, float y) {
    ull r; asm("mov.b64 %0, {%1, %2};" : "=l"(r) : "f"(x), "f"(y)); return r;
}
__device__ __forceinline__ float2 unpack2(ull v) {
    float2 r; asm("mov.b64 {%0, %1}, %2;" : "=f"(r.x), "=f"(r.y) : "l"(v)); return r;
}
__device__ __forceinline__ void fma2(ull& a, ull x, ull y) {
    asm("fma.rn.f32x2 %0, %1, %2, %0;" : "+l"(a) : "l"(x), "l"(y));
}
__device__ __forceinline__ void cp16(unsigned dst, const void* src) {
    asm volatile("cp.async.cg.shared.global [%0], [%1], 16;" :: "r"(dst), "l"(src) : "memory");
}
__device__ __forceinline__ void cp_commit() {
    asm volatile("cp.async.commit_group;" ::: "memory");
}
__device__ __forceinline__ void cp_wait0() {
    asm volatile("cp.async.wait_group 0;" ::: "memory");
}

// ============ K1: qh = Wq q + bq ; U = Wk^T qh / sqrt(dh) ; const = qh.bk/sqrt(dh)
__global__ void __launch_bounds__(256) k1_prep(const float* __restrict__ q,
                                               const float* __restrict__ Wi,
                                               const float* __restrict__ bi) {
    int f = blockIdx.x & (F - 1);
    int b = blockIdx.x >> 3;
    __shared__ float qs[H];
    __shared__ float qhs[H];
    int t = threadIdx.x, lane = t & 31, w = t >> 5;
    qs[t] = q[b * H + t];
    __syncthreads();

    const float* Wq = Wi + (size_t)f * 3 * H * H;
    const float* bq = bi + f * 3 * H;
    for (int i0 = w * 32; i0 < w * 32 + 32; i0 += 4) {
        float s0 = 0.f, s1 = 0.f, s2 = 0.f, s3 = 0.f;
        for (int j = lane; j < H; j += 32) {
            float qv = qs[j];
            s0 = fmaf(Wq[(size_t)(i0 + 0) * H + j], qv, s0);
            s1 = fmaf(Wq[(size_t)(i0 + 1) * H + j], qv, s1);
            s2 = fmaf(Wq[(size_t)(i0 + 2) * H + j], qv, s2);
            s3 = fmaf(Wq[(size_t)(i0 + 3) * H + j], qv, s3);
        }
        #pragma unroll
        for (int o = 16; o; o >>= 1) {
            s0 += __shfl_xor_sync(0xffffffffu, s0, o);
            s1 += __shfl_xor_sync(0xffffffffu, s1, o);
            s2 += __shfl_xor_sync(0xffffffffu, s2, o);
            s3 += __shfl_xor_sync(0xffffffffu, s3, o);
        }
        if (lane == 0) {
            qhs[i0 + 0] = s0 + bq[i0 + 0];
            qhs[i0 + 1] = s1 + bq[i0 + 1];
            qhs[i0 + 2] = s2 + bq[i0 + 2];
            qhs[i0 + 3] = s3 + bq[i0 + 3];
        }
    }
    __syncthreads();

    const float invs = 0.17677669529663687f;
    const float* Wk = Wi + (size_t)f * 3 * H * H + (size_t)H * H;
    float uo[NH];
    #pragma unroll
    for (int h = 0; h < NH; ++h) {
        float s = 0.f;
        #pragma unroll 8
        for (int j = 0; j < DH; ++j)
            s = fmaf(qhs[h * DH + j], Wk[(size_t)(h * DH + j) * H + t], s);
        uo[h] = s * invs;
    }
    float* up = g_U + ((size_t)(b * H + t)) * C + f * NH;
    *(float4*)up       = make_float4(uo[0], uo[1], uo[2], uo[3]);
    *(float4*)(up + 4) = make_float4(uo[4], uo[5], uo[6], uo[7]);

    if (t < NH) {
        const float* bk = bi + f * 3 * H + H;
        float s = 0.f;
        for (int j = 0; j < DH; ++j) s += qhs[t * DH + j] * bk[t * DH + j];
        g_const[b * C + f * NH + t] = s * invs;
    }
}

// ============ K2: 8x8 microtile, 128 threads, min 3 blocks/SM
__global__ void __launch_bounds__(128, 3) k2_scores(const float* __restrict__ docs,
                                                    const float* __restrict__ cw) {
    int b = blockIdx.y;
    int chunk = blockIdx.x;
    int n0 = chunk * TN;
    __shared__ __align__(16) float Ds[32 * 132];
    __shared__ __align__(16) float Us[32 * 64];
    int t = threadIdx.x;
    int rowg = (t >> 3) << 3;
    int colg = (t & 7) << 3;
    ull acc[8][4];
    #pragma unroll
    for (int r = 0; r < 8; ++r)
        #pragma unroll
        for (int p = 0; p < 4; ++p) acc[r][p] = 0ull;

    const float* Db = docs + ((size_t)b * N + n0) * H;
    const float* Ub = g_U + (size_t)b * H * C;
    int lk = (t & 7) << 2;
    int lr = t >> 3;
    int uk = t >> 3;
    int uc = (t & 7) << 3;

    float4 pd[8], pu[2][2];
    #pragma unroll
    for (int it = 0; it < 8; ++it)
        pd[it] = *(const float4*)(Db + (size_t)(lr + (it << 4)) * H + lk);
    #pragma unroll
    for (int iu = 0; iu < 2; ++iu) {
        pu[iu][0] = *(const float4*)(Ub + (size_t)(uk + (iu << 4)) * C + uc);
        pu[iu][1] = *(const float4*)(Ub + (size_t)(uk + (iu << 4)) * C + uc + 4);
    }

    for (int k0 = 0; k0 < H; k0 += 32) {
        if (k0) __syncthreads();
        #pragma unroll
        for (int it = 0; it < 8; ++it) {
            int r = lr + (it << 4);
            Ds[(lk + 0) * 132 + r] = pd[it].x;
            Ds[(lk + 1) * 132 + r] = pd[it].y;
            Ds[(lk + 2) * 132 + r] = pd[it].z;
            Ds[(lk + 3) * 132 + r] = pd[it].w;
        }
        #pragma unroll
        for (int iu = 0; iu < 2; ++iu) {
            *(float4*)&Us[(uk + (iu << 4)) * 64 + uc]     = pu[iu][0];
            *(float4*)&Us[(uk + (iu << 4)) * 64 + uc + 4] = pu[iu][1];
        }
        if (k0 + 32 < H) {
            #pragma unroll
            for (int it = 0; it < 8; ++it)
                pd[it] = *(const float4*)(Db + (size_t)(lr + (it << 4)) * H + (k0 + 32 + lk));
            #pragma unroll
            for (int iu = 0; iu < 2; ++iu) {
                pu[iu][0] = *(const float4*)(Ub + (size_t)(k0 + 32 + uk + (iu << 4)) * C + uc);
                pu[iu][1] = *(const float4*)(Ub + (size_t)(k0 + 32 + uk + (iu << 4)) * C + uc + 4);
            }
        }
        __syncthreads();

        #pragma unroll 4
        for (int k = 0; k < 32; ++k) {
            float4 d0 = *(const float4*)&Ds[k * 132 + rowg];
            float4 d1 = *(const float4*)&Ds[k * 132 + rowg + 4];
            ull u0 = *(const ull*)&Us[k * 64 + colg];
            ull u1 = *(const ull*)&Us[k * 64 + colg + 2];
            ull u2 = *(const ull*)&Us[k * 64 + colg + 4];
            ull u3 = *(const ull*)&Us[k * 64 + colg + 6];
            ull dd;
            dd = pack2(d0.x, d0.x);
            fma2(acc[0][0], dd, u0); fma2(acc[0][1], dd, u1); fma2(acc[0][2], dd, u2); fma2(acc[0][3], dd, u3);
            dd = pack2(d0.y, d0.y);
            fma2(acc[1][0], dd, u0); fma2(acc[1][1], dd, u1); fma2(acc[1][2], dd, u2); fma2(acc[1][3], dd, u3);
            dd = pack2(d0.z, d0.z);
            fma2(acc[2][0], dd, u0); fma2(acc[2][1], dd, u1); fma2(acc[2][2], dd, u2); fma2(acc[2][3], dd, u3);
            dd = pack2(d0.w, d0.w);
            fma2(acc[3][0], dd, u0); fma2(acc[3][1], dd, u1); fma2(acc[3][2], dd, u2); fma2(acc[3][3], dd, u3);
            dd = pack2(d1.x, d1.x);
            fma2(acc[4][0], dd, u0); fma2(acc[4][1], dd, u1); fma2(acc[4][2], dd, u2); fma2(acc[4][3], dd, u3);
            dd = pack2(d1.y, d1.y);
            fma2(acc[5][0], dd, u0); fma2(acc[5][1], dd, u1); fma2(acc[5][2], dd, u2); fma2(acc[5][3], dd, u3);
            dd = pack2(d1.z, d1.z);
            fma2(acc[6][0], dd, u0); fma2(acc[6][1], dd, u1); fma2(acc[6][2], dd, u2); fma2(acc[6][3], dd, u3);
            dd = pack2(d1.w, d1.w);
            fma2(acc[7][0], dd, u0); fma2(acc[7][1], dd, u1); fma2(acc[7][2], dd, u2); fma2(acc[7][3], dd, u3);
        }
    }

    float cst[8];
    #pragma unroll
    for (int c = 0; c < 8; ++c) cst[c] = g_const[b * C + colg + c];
    const float* cwp = cw + (size_t)b * N + n0;
    float o[8][8];
    #pragma unroll
    for (int r = 0; r < 8; ++r) {
        float cwv = cwp[rowg + r];
        #pragma unroll
        for (int p = 0; p < 4; ++p) {
            float2 v = unpack2(acc[r][p]);
            o[r][2 * p]     = fmaf(cwv, v.x, cst[2 * p]);
            o[r][2 * p + 1] = fmaf(cwv, v.y, cst[2 * p + 1]);
        }
        float* sp = g_scores + ((size_t)b * N + n0 + rowg + r) * C + colg;
        *(float4*)sp       = make_float4(o[r][0], o[r][1], o[r][2], o[r][3]);
        *(float4*)(sp + 4) = make_float4(o[r][4], o[r][5], o[r][6], o[r][7]);
    }

    __syncthreads();
    float* red  = Ds;
    float* smax = Us;
    int j = t >> 3;
    #pragma unroll
    for (int c = 0; c < 8; ++c) {
        float lm = o[0][c];
        #pragma unroll
        for (int r = 1; r < 8; ++r) lm = fmaxf(lm, o[r][c]);
        red[j * 65 + colg + c] = lm;
    }
    __syncthreads();
    if (t < 64) {
        float m = -1e30f;
        #pragma unroll
        for (int jj = 0; jj < 16; ++jj) m = fmaxf(m, red[jj * 65 + t]);
        smax[t] = m;
    }
    __syncthreads();
    #pragma unroll
    for (int c = 0; c < 8; ++c) {
        float m = smax[colg + c];
        float ls = 0.f;
        #pragma unroll
        for (int r = 0; r < 8; ++r) ls += __expf(o[r][c] - m);
        red[j * 65 + colg + c] = ls;
    }
    __syncthreads();
    if (t < 64) {
        float l = 0.f;
        #pragma unroll
        for (int jj = 0; jj < 16; ++jj) l += red[jj * 65 + t];
        g_part[(b * NCHUNK + chunk) * C + t] = make_float2(smax[t], l);
    }
}

// ============ K4: cp.async docs, 2 blocks/SM
__global__ void __launch_bounds__(256, 2) k4_wgemm(const float* __restrict__ docs,
                                                   const float* __restrict__ cw) {
    int b = blockIdx.y, ns = blockIdx.x;
    int n0 = ns * (N / NSPLIT);
    __shared__ __align__(16) float Dn[32 * 260];
    __shared__ __align__(16) float As[32 * 64];
    __shared__ float msh[64], ilh[64];
    int t = threadIdx.x;

    if (t < 64) {
        float2 pc[NCHUNK];
        float m = -1e30f;
        #pragma unroll
        for (int ch = 0; ch < NCHUNK; ++ch) {
            pc[ch] = g_part[(b * NCHUNK + ch) * C + t];
            m = fmaxf(m, pc[ch].x);
        }
        float l = 0.f;
        #pragma unroll
        for (int ch = 0; ch < NCHUNK; ++ch) l += pc[ch].y * __expf(pc[ch].x - m);
        msh[t] = m; ilh[t] = 1.0f / l;
    }
    __syncthreads();
    float mC = msh[t & 63], iC = ilh[t & 63];

    int rowg = (t >> 3) << 3;
    int colg = (t & 7) << 3;
    ull acc[8][4];
    #pragma unroll
    for (int r = 0; r < 8; ++r)
        #pragma unroll
        for (int p = 0; p < 4; ++p) acc[r][p] = 0ull;

    float ps[8], pcw[8];
    int kq = (t & 63) << 2;
    int nnb = t >> 6;
    unsigned dnb = (unsigned)__cvta_generic_to_shared(Dn);
    unsigned dn_dst = dnb + (unsigned)(nnb * 1040 + (kq << 2));

    {
        const float* Sg = g_scores + ((size_t)b * N + n0) * C;
        const float* Cg = cw + (size_t)b * N + n0;
        #pragma unroll
        for (int i = 0; i < 8; ++i) {
            int nn = nnb + (i << 2);
            ps[i] = Sg[(size_t)nn * C + (t & 63)];
            pcw[i] = Cg[nn];
        }
    }

    for (int nc = 0; nc < N / NSPLIT; nc += 32) {
        if (nc) __syncthreads();
        const float* Dg = docs + ((size_t)b * N + n0 + nc) * H;
        #pragma unroll
        for (int i = 0; i < 8; ++i)
            cp16(dn_dst + (unsigned)(i * 4 * 1040), Dg + (size_t)(nnb + (i << 2)) * H + kq);
        cp_commit();

        #pragma unroll
        for (int i = 0; i < 8; ++i) {
            int nn = nnb + (i << 2);
            As[nn * 64 + (t & 63)] = __expf(ps[i] - mC) * iC * pcw[i];
        }
        if (nc + 32 < N / NSPLIT) {
            const float* Sg = g_scores + ((size_t)b * N + n0 + nc + 32) * C;
            const float* Cg = cw + (size_t)b * N + n0 + nc + 32;
            #pragma unroll
            for (int i = 0; i < 8; ++i) {
                int nn = nnb + (i << 2);
                ps[i] = Sg[(size_t)nn * C + (t & 63)];
                pcw[i] = Cg[nn];
            }
        }
        cp_wait0();
        __syncthreads();

        #pragma unroll 4
        for (int nn = 0; nn < 32; ++nn) {
            float4 d0 = *(const float4*)&Dn[nn * 260 + rowg];
            float4 d1 = *(const float4*)&Dn[nn * 260 + rowg + 4];
            ull u0 = *(const ull*)&As[nn * 64 + colg];
            ull u1 = *(const ull*)&As[nn * 64 + colg + 2];
            ull u2 = *(const ull*)&As[nn * 64 + colg + 4];
            ull u3 = *(const ull*)&As[nn * 64 + colg + 6];
            ull dd;
            dd = pack2(d0.x, d0.x);
            fma2(acc[0][0], dd, u0); fma2(acc[0][1], dd, u1); fma2(acc[0][2], dd, u2); fma2(acc[0][3], dd, u3);
            dd = pack2(d0.y, d0.y);
            fma2(acc[1][0], dd, u0); fma2(acc[1][1], dd, u1); fma2(acc[1][2], dd, u2); fma2(acc[1][3], dd, u3);
            dd = pack2(d0.z, d0.z);
            fma2(acc[2][0], dd, u0); fma2(acc[2][1], dd, u1); fma2(acc[2][2], dd, u2); fma2(acc[2][3], dd, u3);
            dd = pack2(d0.w, d0.w);
            fma2(acc[3][0], dd, u0); fma2(acc[3][1], dd, u1); fma2(acc[3][2], dd, u2); fma2(acc[3][3], dd, u3);
            dd = pack2(d1.x, d1.x);
            fma2(acc[4][0], dd, u0); fma2(acc[4][1], dd, u1); fma2(acc[4][2], dd, u2); fma2(acc[4][3], dd, u3);
            dd = pack2(d1.y, d1.y);
            fma2(acc[5][0], dd, u0); fma2(acc[5][1], dd, u1); fma2(acc[5][2], dd, u2); fma2(acc[5][3], dd, u3);
            dd = pack2(d1.z, d1.z);
            fma2(acc[6][0], dd, u0); fma2(acc[6][1], dd, u1); fma2(acc[6][2], dd, u2); fma2(acc[6][3], dd, u3);
            dd = pack2(d1.w, d1.w);
            fma2(acc[7][0], dd, u0); fma2(acc[7][1], dd, u1); fma2(acc[7][2], dd, u2); fma2(acc[7][3], dd, u3);
        }
    }

    float* Wp = g_Wpart + ((size_t)(b * NSPLIT + ns)) * H * C;
    #pragma unroll
    for (int r = 0; r < 8; ++r) {
        float o[8];
        #pragma unroll
        for (int p = 0; p < 4; ++p) {
            float2 v = unpack2(acc[r][p]);
            o[2 * p] = v.x; o[2 * p + 1] = v.y;
        }
        float* wp = Wp + (size_t)(rowg + r) * C + colg;
        *(float4*)wp       = make_float4(o[0], o[1], o[2], o[3]);
        *(float4*)(wp + 4) = make_float4(o[4], o[5], o[6], o[7]);
    }
}

// ============ kT: 256 blocks (b, tk): reduce partials + transpose -> g_WT
__global__ void __launch_bounds__(256) kT_red() {
    int b  = blockIdx.x >> 3;
    int tk = blockIdx.x & 7;
    int t = threadIdx.x;
    __shared__ __align__(16) float S[32 * 68];
    const float* base = g_Wpart + (size_t)b * NSPLIT * (H * C);

    {
        int kk = t >> 3, cq = (t & 7) << 3;
        const float* p0 = base + (size_t)(tk * 32 + kk) * C + cq;
        float4 a0 = *(const float4*)p0;
        float4 a1 = *(const float4*)(p0 + 4);
        #pragma unroll
        for (int p = 1; p < NSPLIT; ++p) {
            const float* pp = p0 + (size_t)p * H * C;
            float4 b0 = *(const float4*)pp;
            float4 b1 = *(const float4*)(pp + 4);
            a0.x += b0.x; a0.y += b0.y; a0.z += b0.z; a0.w += b0.w;
            a1.x += b1.x; a1.y += b1.y; a1.z += b1.z; a1.w += b1.w;
        }
        *(float4*)&S[kk * 68 + cq]     = a0;
        *(float4*)&S[kk * 68 + cq + 4] = a1;
    }
    __syncthreads();
    {
        int cc = t >> 2, kq = (t & 3) << 3;
        float v[8];
        #pragma unroll
        for (int i = 0; i < 8; ++i) v[i] = S[(kq + i) * 68 + cc];
        float* wt = g_WT + ((size_t)(b * C + cc)) * H + tk * 32 + kq;
        *(float4*)wt       = make_float4(v[0], v[1], v[2], v[3]);
        *(float4*)(wt + 4) = make_float4(v[4], v[5], v[6], v[7]);
    }
}

// ============ kctx: per (f,h): CTX[32b x 32i]
__global__ void __launch_bounds__(256) kctx(const float* __restrict__ Wi,
                                            const float* __restrict__ bi) {
    int f = blockIdx.x >> 3;
    int h = blockIdx.x & 7;
    int c = f * NH + h;
    int t = threadIdx.x;
    __shared__ __align__(16) float Vv[32 * 132];
    __shared__ __align__(16) float Wb[32 * 132];

    const float* Wv = Wi + (size_t)f * 3 * H * H + (size_t)2 * H * H + (size_t)(h * 32) * H;
    int bb = t & 31, w = t >> 5, ii0 = w * 4;
    ull acc[4] = {0ull, 0ull, 0ull, 0ull};

    for (int kc = 0; kc < H; kc += 128) {
        if (kc) __syncthreads();
        #pragma unroll
        for (int i = 0; i < 4; ++i) {
            int idx = t + (i << 8);
            int rr = idx >> 5, kq = (idx & 31) << 2;
            *(float4*)&Vv[rr * 132 + kq] = *(const float4*)(Wv + (size_t)rr * H + kc + kq);
            *(float4*)&Wb[rr * 132 + kq] = *(const float4*)(g_WT + ((size_t)(rr * C + c)) * H + kc + kq);
        }
        __syncthreads();
        #pragma unroll 8
        for (int kp = 0; kp < 64; ++kp) {
            ull x = *(const ull*)&Wb[bb * 132 + kp * 2];
            fma2(acc[0], x, *(const ull*)&Vv[(ii0 + 0) * 132 + kp * 2]);
            fma2(acc[1], x, *(const ull*)&Vv[(ii0 + 1) * 132 + kp * 2]);
            fma2(acc[2], x, *(const ull*)&Vv[(ii0 + 2) * 132 + kp * 2]);
            fma2(acc[3], x, *(const ull*)&Vv[(ii0 + 3) * 132 + kp * 2]);
        }
    }

    const float* bv = bi + f * 3 * H + 2 * H + h * 32;
    #pragma unroll
    for (int j = 0; j < 4; ++j) {
        float2 v = unpack2(acc[j]);
        g_ctx[((size_t)(f * B + bb)) * H + h * 32 + ii0 + j] = v.x + v.y + bv[ii0 + j];
    }
}

// ============ kho: 64 blocks (f, 32-wide i-tile): HO = CTX @ Wo^T + bo
__global__ void __launch_bounds__(256) kho(const float* __restrict__ Wo,
                                           const float* __restrict__ bo) {
    int f = blockIdx.x >> 3;
    int i0 = (blockIdx.x & 7) * 32;
    int t = threadIdx.x;
    __shared__ __align__(16) float Cs[32 * 260];
    __shared__ __align__(16) float Wos[32 * 36];

    #pragma unroll
    for (int i = 0; i < 8; ++i) {
        int idx = t + (i << 8);
        int rr = idx >> 6, jq = (idx & 63) << 2;
        *(float4*)&Cs[rr * 260 + jq] = *(const float4*)(g_ctx + ((size_t)(f * B + rr)) * H + jq);
    }

    int bb = t >> 3, ig = (t & 7) << 2;
    ull acc[2] = {0ull, 0ull};
    const float* Wof = Wo + (size_t)f * H * H;

    for (int jc = 0; jc < H; jc += 32) {
        __syncthreads();
        {
            int ii = t >> 3, jq = (t & 7) << 2;
            float4 v0 = *(const float4*)(Wof + (size_t)(i0 + ii) * H + jc + jq);
            Wos[(jq + 0) * 36 + ii] = v0.x;
            Wos[(jq + 1) * 36 + ii] = v0.y;
            Wos[(jq + 2) * 36 + ii] = v0.z;
            Wos[(jq + 3) * 36 + ii] = v0.w;
        }
        __syncthreads();
        #pragma unroll 8
        for (int jj = 0; jj < 32; ++jj) {
            float x = Cs[bb * 260 + jc + jj];
            ull xx = pack2(x, x);
            fma2(acc[0], xx, *(const ull*)&Wos[jj * 36 + ig]);
            fma2(acc[1], xx, *(const ull*)&Wos[jj * 36 + ig + 2]);
        }
    }

    const float* bof = bo + f * H + i0 + ig;
    float2 v0 = unpack2(acc[0]), v1 = unpack2(acc[1]);
    float* hp = g_ho + ((size_t)(f * B + bb)) * H + i0 + ig;
    *(float4*)hp = make_float4(v0.x + bof[0], v0.y + bof[1], v1.x + bof[2], v1.y + bof[3]);
}

// ============ k_meta3: all 3 meta steps fused; 64 blocks x 4 rows
// X'[r] = X[r] + X[r] @ M_s, rows independent. X kept transposed in smem.
__global__ void __launch_bounds__(256) k_meta3(const float* __restrict__ ho_in,
                                               const float* __restrict__ M,
                                               float* __restrict__ ho_out) {
    int r0 = blockIdx.x * 4;
    int t = threadIdx.x;
    __shared__ __align__(16) float Xt[256 * 6];    // [k][r] padded to 6
    __shared__ __align__(16) float Ms[32 * 260];

    // load 4 rows, transpose into Xt[k][r]
    {
        int r = t & 3, kq = (t >> 2) << 2;   // 64 k-groups of 4
        float4 a = *(const float4*)(ho_in + (size_t)(r0 + r) * H + kq);
        Xt[(kq + 0) * 6 + r] = a.x;
        Xt[(kq + 1) * 6 + r] = a.y;
        Xt[(kq + 2) * 6 + r] = a.z;
        Xt[(kq + 3) * 6 + r] = a.w;
    }
    __syncthreads();

    for (int s = 0; s < STEPS; ++s) {
        const float* Msrc = M + (size_t)s * H * H;
        ull acc[2] = {0ull, 0ull};
        for (int kc = 0; kc < H; kc += 32) {
            if (kc | s) __syncthreads();     // protect Ms reuse / Xt rewrite
            #pragma unroll
            for (int i = 0; i < 8; ++i) {
                int idx = t + (i << 8);
                int rr = idx >> 6, cq = (idx & 63) << 2;
                *(float4*)&Ms[rr * 260 + cq] = *(const float4*)(Msrc + (size_t)(kc + rr) * H + cq);
            }
            __syncthreads();
            #pragma unroll 4
            for (int k = 0; k < 32; ++k) {
                float m = Ms[k * 260 + t];
                ull mm = pack2(m, m);
                const float* xk = &Xt[(kc + k) * 6];
                fma2(acc[0], *(const ull*)(xk + 0), mm);
                fma2(acc[1], *(const ull*)(xk + 2), mm);
            }
        }
        // y[r] = acc + x_old[r]; x_old[r][col t] = Xt[t][r]
        float y[4];
        {
            float2 v0 = unpack2(acc[0]), v1 = unpack2(acc[1]);
            y[0] = v0.x + Xt[t * 6 + 0];
            y[1] = v0.y + Xt[t * 6 + 1];
            y[2] = v1.x + Xt[t * 6 + 2];
            y[3] = v1.y + Xt[t * 6 + 3];
        }
        __syncthreads();                     // all fma reads of Xt done
        #pragma unroll
        for (int r = 0; r < 4; ++r) Xt[t * 6 + r] = y[r];
    }
    __syncthreads();
    {
        // coalesced store: column t of each row
        #pragma unroll
        for (int r = 0; r < 4; ++r)
            ho_out[(size_t)(r0 + r) * H + t] = Xt[t * 6 + r];
    }
}

// ============ K5b: strategy softmax + combine
__global__ void __launch_bounds__(256) k5b_out(const float* __restrict__ q,
                                               const float* __restrict__ sw,
                                               const float* __restrict__ sb,
                                               float* __restrict__ out) {
    int b = blockIdx.x;
    int t = threadIdx.x, lane = t & 31, w = t >> 5;
    __shared__ float qs[H];
    __shared__ float lg[F];
    __shared__ float pr[F];
    qs[t] = q[b * H + t];
    __syncthreads();
    {
        float s = 0.f;
        for (int j = lane; j < H; j += 32) s = fmaf(sw[(size_t)w * H + j], qs[j], s);
        #pragma unroll
        for (int o = 16; o; o >>= 1) s += __shfl_xor_sync(0xffffffffu, s, o);
        if (lane == 0) lg[w] = s + sb[w];
    }
    __syncthreads();
    if (t == 0) {
        float m = lg[0];
        #pragma unroll
        for (int f2 = 1; f2 < F; ++f2) m = fmaxf(m, lg[f2]);
        float sum = 0.f;
        #pragma unroll
        for (int f2 = 0; f2 < F; ++f2) { pr[f2] = __expf(lg[f2] - m); sum += pr[f2]; }
        float inv = 1.0f / sum;
        #pragma unroll
        for (int f2 = 0; f2 < F; ++f2) pr[f2] *= inv;
    }
    __syncthreads();
    float o = 0.f;
    #pragma unroll
    for (int f2 = 0; f2 < F; ++f2)
        o = fmaf(pr[f2], g_ho2[((size_t)(f2 * B + b)) * H + t], o);
    out[b * H + t] = o;
}

extern "C" void kernel_launch(void* const* d_in, const int* in_sizes, int n_in,
                              void* d_out, int out_size) {
    const float* q    = (const float*)d_in[0];
    const float* docs = (const float*)d_in[1];
    const float* cw   = (const float*)d_in[2];
    const float* Wi   = (const float*)d_in[4];
    const float* bi   = (const float*)d_in[5];
    const float* Wo   = (const float*)d_in[6];
    const float* bo   = (const float*)d_in[7];
    const float* sw   = (const float*)d_in[8];
    const float* sb   = (const float*)d_in[9];
    const float* M    = (const float*)d_in[10];
    float* out = (float*)d_out;

    float* ho;  cudaGetSymbolAddress((void**)&ho,  g_ho);
    float* ho2; cudaGetSymbolAddress((void**)&ho2, g_ho2);

    k1_prep<<<B * F, 256>>>(q, Wi, bi);
    k2_scores<<<dim3(NCHUNK, B), 128>>>(docs, cw);
    k4_wgemm<<<dim3(NSPLIT, B), 256>>>(docs, cw);
    kT_red<<<B * 8, 256>>>();                         // launch #4 -> profiled
    kctx<<<F * NH, 256>>>(Wi, bi);
    kho<<<F * 8, 256>>>(Wo, bo);
    k_meta3<<<64, 256>>>(ho, M, ho2);
    k5b_out<<<B, 256>>>(q, sw, sb, out);
}

// round 17
// speedup vs baseline: 1.0806x; 1.0806x over previous
#include <cuda_runtime.h>
#include <math.h>

#define B 32
#define N 2048
#define H 256
#define F 8
#define NH 8
#define DH 32
#define C 64
#define STEPS 3
#define NSPLIT 8
#define TN 128
#define NCHUNK 16

typedef unsigned long long ull;

__device__ float  g_U[B * H * C];
__device__ float  g_const[B * C];
__device__ float  g_scores[(size_t)B * N * C];
__device__ float2 g_part[B * NCHUNK * C];
__device__ float  g_Wpart[(size_t)B * NSPLIT * H * C];
__device__ float  g_WT[B * C * H];
__device__ float  g_ctx[F * B * H];
__device__ float  g_ho[F * B * H];
__device__ float  g_ho2[F * B * H];

__device__ __forceinline__ ull pack2(float x, float y) {
    ull r; asm("mov.b64 %0, {%1, %2};" : "=l"(r) : "f"(x), "f"(y)); return r;
}
__device__ __forceinline__ float2 unpack2(ull v) {
    float2 r; asm("mov.b64 {%0, %1}, %2;" : "=f"(r.x), "=f"(r.y) : "l"(v)); return r;
}
__device__ __forceinline__ void fma2(ull& a, ull x, ull y) {
    asm("fma.rn.f32x2 %0, %1, %2, %0;" : "+l"(a) : "l"(x), "l"(y));
}
__device__ __forceinline__ void cp16(unsigned dst, const void* src) {
    asm volatile("cp.async.cg.shared.global [%0], [%1], 16;" :: "r"(dst), "l"(src) : "memory");
}
__device__ __forceinline__ void cp_commit() {
    asm volatile("cp.async.commit_group;" ::: "memory");
}
__device__ __forceinline__ void cp_wait0() {
    asm volatile("cp.async.wait_group 0;" ::: "memory");
}

// ============ K1: qh = Wq q + bq ; U = Wk^T qh / sqrt(dh) ; const = qh.bk/sqrt(dh)
__global__ void __launch_bounds__(256) k1_prep(const float* __restrict__ q,
                                               const float* __restrict__ Wi,
                                               const float* __restrict__ bi) {
    int f = blockIdx.x & (F - 1);
    int b = blockIdx.x >> 3;
    __shared__ float qs[H];
    __shared__ float qhs[H];
    int t = threadIdx.x, lane = t & 31, w = t >> 5;
    qs[t] = q[b * H + t];
    __syncthreads();

    const float* Wq = Wi + (size_t)f * 3 * H * H;
    const float* bq = bi + f * 3 * H;
    for (int i0 = w * 32; i0 < w * 32 + 32; i0 += 4) {
        float s0 = 0.f, s1 = 0.f, s2 = 0.f, s3 = 0.f;
        for (int j = lane; j < H; j += 32) {
            float qv = qs[j];
            s0 = fmaf(Wq[(size_t)(i0 + 0) * H + j], qv, s0);
            s1 = fmaf(Wq[(size_t)(i0 + 1) * H + j], qv, s1);
            s2 = fmaf(Wq[(size_t)(i0 + 2) * H + j], qv, s2);
            s3 = fmaf(Wq[(size_t)(i0 + 3) * H + j], qv, s3);
        }
        #pragma unroll
        for (int o = 16; o; o >>= 1) {
            s0 += __shfl_xor_sync(0xffffffffu, s0, o);
            s1 += __shfl_xor_sync(0xffffffffu, s1, o);
            s2 += __shfl_xor_sync(0xffffffffu, s2, o);
            s3 += __shfl_xor_sync(0xffffffffu, s3, o);
        }
        if (lane == 0) {
            qhs[i0 + 0] = s0 + bq[i0 + 0];
            qhs[i0 + 1] = s1 + bq[i0 + 1];
            qhs[i0 + 2] = s2 + bq[i0 + 2];
            qhs[i0 + 3] = s3 + bq[i0 + 3];
        }
    }
    __syncthreads();

    const float invs = 0.17677669529663687f;
    const float* Wk = Wi + (size_t)f * 3 * H * H + (size_t)H * H;
    float uo[NH];
    #pragma unroll
    for (int h = 0; h < NH; ++h) {
        float s = 0.f;
        #pragma unroll 8
        for (int j = 0; j < DH; ++j)
            s = fmaf(qhs[h * DH + j], Wk[(size_t)(h * DH + j) * H + t], s);
        uo[h] = s * invs;
    }
    float* up = g_U + ((size_t)(b * H + t)) * C + f * NH;
    *(float4*)up       = make_float4(uo[0], uo[1], uo[2], uo[3]);
    *(float4*)(up + 4) = make_float4(uo[4], uo[5], uo[6], uo[7]);

    if (t < NH) {
        const float* bk = bi + f * 3 * H + H;
        float s = 0.f;
        for (int j = 0; j < DH; ++j) s += qhs[t * DH + j] * bk[t * DH + j];
        g_const[b * C + f * NH + t] = s * invs;
    }
}

// ============ K2: 8x8 microtile, 128 threads, min 3 blocks/SM; LDS.128 U-loads
__global__ void __launch_bounds__(128, 3) k2_scores(const float* __restrict__ docs,
                                                    const float* __restrict__ cw) {
    int b = blockIdx.y;
    int chunk = blockIdx.x;
    int n0 = chunk * TN;
    __shared__ __align__(16) float Ds[32 * 132];
    __shared__ __align__(16) float Us[32 * 64];
    int t = threadIdx.x;
    int rowg = (t >> 3) << 3;
    int colg = (t & 7) << 3;
    ull acc[8][4];
    #pragma unroll
    for (int r = 0; r < 8; ++r)
        #pragma unroll
        for (int p = 0; p < 4; ++p) acc[r][p] = 0ull;

    const float* Db = docs + ((size_t)b * N + n0) * H;
    const float* Ub = g_U + (size_t)b * H * C;
    int lk = (t & 7) << 2;
    int lr = t >> 3;
    int uk = t >> 3;
    int uc = (t & 7) << 3;

    float4 pd[8], pu[2][2];
    #pragma unroll
    for (int it = 0; it < 8; ++it)
        pd[it] = *(const float4*)(Db + (size_t)(lr + (it << 4)) * H + lk);
    #pragma unroll
    for (int iu = 0; iu < 2; ++iu) {
        pu[iu][0] = *(const float4*)(Ub + (size_t)(uk + (iu << 4)) * C + uc);
        pu[iu][1] = *(const float4*)(Ub + (size_t)(uk + (iu << 4)) * C + uc + 4);
    }

    for (int k0 = 0; k0 < H; k0 += 32) {
        if (k0) __syncthreads();
        #pragma unroll
        for (int it = 0; it < 8; ++it) {
            int r = lr + (it << 4);
            Ds[(lk + 0) * 132 + r] = pd[it].x;
            Ds[(lk + 1) * 132 + r] = pd[it].y;
            Ds[(lk + 2) * 132 + r] = pd[it].z;
            Ds[(lk + 3) * 132 + r] = pd[it].w;
        }
        #pragma unroll
        for (int iu = 0; iu < 2; ++iu) {
            *(float4*)&Us[(uk + (iu << 4)) * 64 + uc]     = pu[iu][0];
            *(float4*)&Us[(uk + (iu << 4)) * 64 + uc + 4] = pu[iu][1];
        }
        if (k0 + 32 < H) {
            #pragma unroll
            for (int it = 0; it < 8; ++it)
                pd[it] = *(const float4*)(Db + (size_t)(lr + (it << 4)) * H + (k0 + 32 + lk));
            #pragma unroll
            for (int iu = 0; iu < 2; ++iu) {
                pu[iu][0] = *(const float4*)(Ub + (size_t)(k0 + 32 + uk + (iu << 4)) * C + uc);
                pu[iu][1] = *(const float4*)(Ub + (size_t)(k0 + 32 + uk + (iu << 4)) * C + uc + 4);
            }
        }
        __syncthreads();

        #pragma unroll 4
        for (int k = 0; k < 32; ++k) {
            float4 d0 = *(const float4*)&Ds[k * 132 + rowg];
            float4 d1 = *(const float4*)&Ds[k * 132 + rowg + 4];
            double2 ua = *(const double2*)&Us[k * 64 + colg];
            double2 ub = *(const double2*)&Us[k * 64 + colg + 4];
            ull u0 = __double_as_longlong(ua.x);
            ull u1 = __double_as_longlong(ua.y);
            ull u2 = __double_as_longlong(ub.x);
            ull u3 = __double_as_longlong(ub.y);
            ull dd;
            dd = pack2(d0.x, d0.x);
            fma2(acc[0][0], dd, u0); fma2(acc[0][1], dd, u1); fma2(acc[0][2], dd, u2); fma2(acc[0][3], dd, u3);
            dd = pack2(d0.y, d0.y);
            fma2(acc[1][0], dd, u0); fma2(acc[1][1], dd, u1); fma2(acc[1][2], dd, u2); fma2(acc[1][3], dd, u3);
            dd = pack2(d0.z, d0.z);
            fma2(acc[2][0], dd, u0); fma2(acc[2][1], dd, u1); fma2(acc[2][2], dd, u2); fma2(acc[2][3], dd, u3);
            dd = pack2(d0.w, d0.w);
            fma2(acc[3][0], dd, u0); fma2(acc[3][1], dd, u1); fma2(acc[3][2], dd, u2); fma2(acc[3][3], dd, u3);
            dd = pack2(d1.x, d1.x);
            fma2(acc[4][0], dd, u0); fma2(acc[4][1], dd, u1); fma2(acc[4][2], dd, u2); fma2(acc[4][3], dd, u3);
            dd = pack2(d1.y, d1.y);
            fma2(acc[5][0], dd, u0); fma2(acc[5][1], dd, u1); fma2(acc[5][2], dd, u2); fma2(acc[5][3], dd, u3);
            dd = pack2(d1.z, d1.z);
            fma2(acc[6][0], dd, u0); fma2(acc[6][1], dd, u1); fma2(acc[6][2], dd, u2); fma2(acc[6][3], dd, u3);
            dd = pack2(d1.w, d1.w);
            fma2(acc[7][0], dd, u0); fma2(acc[7][1], dd, u1); fma2(acc[7][2], dd, u2); fma2(acc[7][3], dd, u3);
        }
    }

    float cst[8];
    #pragma unroll
    for (int c = 0; c < 8; ++c) cst[c] = g_const[b * C + colg + c];
    const float* cwp = cw + (size_t)b * N + n0;
    float o[8][8];
    #pragma unroll
    for (int r = 0; r < 8; ++r) {
        float cwv = cwp[rowg + r];
        #pragma unroll
        for (int p = 0; p < 4; ++p) {
            float2 v = unpack2(acc[r][p]);
            o[r][2 * p]     = fmaf(cwv, v.x, cst[2 * p]);
            o[r][2 * p + 1] = fmaf(cwv, v.y, cst[2 * p + 1]);
        }
        float* sp = g_scores + ((size_t)b * N + n0 + rowg + r) * C + colg;
        *(float4*)sp       = make_float4(o[r][0], o[r][1], o[r][2], o[r][3]);
        *(float4*)(sp + 4) = make_float4(o[r][4], o[r][5], o[r][6], o[r][7]);
    }

    __syncthreads();
    float* red  = Ds;
    float* smax = Us;
    int j = t >> 3;
    #pragma unroll
    for (int c = 0; c < 8; ++c) {
        float lm = o[0][c];
        #pragma unroll
        for (int r = 1; r < 8; ++r) lm = fmaxf(lm, o[r][c]);
        red[j * 65 + colg + c] = lm;
    }
    __syncthreads();
    if (t < 64) {
        float m = -1e30f;
        #pragma unroll
        for (int jj = 0; jj < 16; ++jj) m = fmaxf(m, red[jj * 65 + t]);
        smax[t] = m;
    }
    __syncthreads();
    #pragma unroll
    for (int c = 0; c < 8; ++c) {
        float m = smax[colg + c];
        float ls = 0.f;
        #pragma unroll
        for (int r = 0; r < 8; ++r) ls += __expf(o[r][c] - m);
        red[j * 65 + colg + c] = ls;
    }
    __syncthreads();
    if (t < 64) {
        float l = 0.f;
        #pragma unroll
        for (int jj = 0; jj < 16; ++jj) l += red[jj * 65 + t];
        g_part[(b * NCHUNK + chunk) * C + t] = make_float2(smax[t], l);
    }
}

// ============ K4: cp.async docs, 2 blocks/SM; LDS.128 As-loads
__global__ void __launch_bounds__(256, 2) k4_wgemm(const float* __restrict__ docs,
                                                   const float* __restrict__ cw) {
    int b = blockIdx.y, ns = blockIdx.x;
    int n0 = ns * (N / NSPLIT);
    __shared__ __align__(16) float Dn[32 * 260];
    __shared__ __align__(16) float As[32 * 64];
    __shared__ float msh[64], ilh[64];
    int t = threadIdx.x;

    if (t < 64) {
        float2 pc[NCHUNK];
        float m = -1e30f;
        #pragma unroll
        for (int ch = 0; ch < NCHUNK; ++ch) {
            pc[ch] = g_part[(b * NCHUNK + ch) * C + t];
            m = fmaxf(m, pc[ch].x);
        }
        float l = 0.f;
        #pragma unroll
        for (int ch = 0; ch < NCHUNK; ++ch) l += pc[ch].y * __expf(pc[ch].x - m);
        msh[t] = m; ilh[t] = 1.0f / l;
    }
    __syncthreads();
    float mC = msh[t & 63], iC = ilh[t & 63];

    int rowg = (t >> 3) << 3;
    int colg = (t & 7) << 3;
    ull acc[8][4];
    #pragma unroll
    for (int r = 0; r < 8; ++r)
        #pragma unroll
        for (int p = 0; p < 4; ++p) acc[r][p] = 0ull;

    float ps[8], pcw[8];
    int kq = (t & 63) << 2;
    int nnb = t >> 6;
    unsigned dnb = (unsigned)__cvta_generic_to_shared(Dn);
    unsigned dn_dst = dnb + (unsigned)(nnb * 1040 + (kq << 2));

    {
        const float* Sg = g_scores + ((size_t)b * N + n0) * C;
        const float* Cg = cw + (size_t)b * N + n0;
        #pragma unroll
        for (int i = 0; i < 8; ++i) {
            int nn = nnb + (i << 2);
            ps[i] = Sg[(size_t)nn * C + (t & 63)];
            pcw[i] = Cg[nn];
        }
    }

    for (int nc = 0; nc < N / NSPLIT; nc += 32) {
        if (nc) __syncthreads();
        const float* Dg = docs + ((size_t)b * N + n0 + nc) * H;
        #pragma unroll
        for (int i = 0; i < 8; ++i)
            cp16(dn_dst + (unsigned)(i * 4 * 1040), Dg + (size_t)(nnb + (i << 2)) * H + kq);
        cp_commit();

        #pragma unroll
        for (int i = 0; i < 8; ++i) {
            int nn = nnb + (i << 2);
            As[nn * 64 + (t & 63)] = __expf(ps[i] - mC) * iC * pcw[i];
        }
        if (nc + 32 < N / NSPLIT) {
            const float* Sg = g_scores + ((size_t)b * N + n0 + nc + 32) * C;
            const float* Cg = cw + (size_t)b * N + n0 + nc + 32;
            #pragma unroll
            for (int i = 0; i < 8; ++i) {
                int nn = nnb + (i << 2);
                ps[i] = Sg[(size_t)nn * C + (t & 63)];
                pcw[i] = Cg[nn];
            }
        }
        cp_wait0();
        __syncthreads();

        #pragma unroll 4
        for (int nn = 0; nn < 32; ++nn) {
            float4 d0 = *(const float4*)&Dn[nn * 260 + rowg];
            float4 d1 = *(const float4*)&Dn[nn * 260 + rowg + 4];
            double2 ua = *(const double2*)&As[nn * 64 + colg];
            double2 ub = *(const double2*)&As[nn * 64 + colg + 4];
            ull u0 = __double_as_longlong(ua.x);
            ull u1 = __double_as_longlong(ua.y);
            ull u2 = __double_as_longlong(ub.x);
            ull u3 = __double_as_longlong(ub.y);
            ull dd;
            dd = pack2(d0.x, d0.x);
            fma2(acc[0][0], dd, u0); fma2(acc[0][1], dd, u1); fma2(acc[0][2], dd, u2); fma2(acc[0][3], dd, u3);
            dd = pack2(d0.y, d0.y);
            fma2(acc[1][0], dd, u0); fma2(acc[1][1], dd, u1); fma2(acc[1][2], dd, u2); fma2(acc[1][3], dd, u3);
            dd = pack2(d0.z, d0.z);
            fma2(acc[2][0], dd, u0); fma2(acc[2][1], dd, u1); fma2(acc[2][2], dd, u2); fma2(acc[2][3], dd, u3);
            dd = pack2(d0.w, d0.w);
            fma2(acc[3][0], dd, u0); fma2(acc[3][1], dd, u1); fma2(acc[3][2], dd, u2); fma2(acc[3][3], dd, u3);
            dd = pack2(d1.x, d1.x);
            fma2(acc[4][0], dd, u0); fma2(acc[4][1], dd, u1); fma2(acc[4][2], dd, u2); fma2(acc[4][3], dd, u3);
            dd = pack2(d1.y, d1.y);
            fma2(acc[5][0], dd, u0); fma2(acc[5][1], dd, u1); fma2(acc[5][2], dd, u2); fma2(acc[5][3], dd, u3);
            dd = pack2(d1.z, d1.z);
            fma2(acc[6][0], dd, u0); fma2(acc[6][1], dd, u1); fma2(acc[6][2], dd, u2); fma2(acc[6][3], dd, u3);
            dd = pack2(d1.w, d1.w);
            fma2(acc[7][0], dd, u0); fma2(acc[7][1], dd, u1); fma2(acc[7][2], dd, u2); fma2(acc[7][3], dd, u3);
        }
    }

    float* Wp = g_Wpart + ((size_t)(b * NSPLIT + ns)) * H * C;
    #pragma unroll
    for (int r = 0; r < 8; ++r) {
        float o[8];
        #pragma unroll
        for (int p = 0; p < 4; ++p) {
            float2 v = unpack2(acc[r][p]);
            o[2 * p] = v.x; o[2 * p + 1] = v.y;
        }
        float* wp = Wp + (size_t)(rowg + r) * C + colg;
        *(float4*)wp       = make_float4(o[0], o[1], o[2], o[3]);
        *(float4*)(wp + 4) = make_float4(o[4], o[5], o[6], o[7]);
    }
}

// ============ kT: 256 blocks (b, tk): reduce partials + transpose -> g_WT
__global__ void __launch_bounds__(256) kT_red() {
    int b  = blockIdx.x >> 3;
    int tk = blockIdx.x & 7;
    int t = threadIdx.x;
    __shared__ __align__(16) float S[32 * 68];
    const float* base = g_Wpart + (size_t)b * NSPLIT * (H * C);

    {
        int kk = t >> 3, cq = (t & 7) << 3;
        const float* p0 = base + (size_t)(tk * 32 + kk) * C + cq;
        float4 a0 = *(const float4*)p0;
        float4 a1 = *(const float4*)(p0 + 4);
        #pragma unroll
        for (int p = 1; p < NSPLIT; ++p) {
            const float* pp = p0 + (size_t)p * H * C;
            float4 b0 = *(const float4*)pp;
            float4 b1 = *(const float4*)(pp + 4);
            a0.x += b0.x; a0.y += b0.y; a0.z += b0.z; a0.w += b0.w;
            a1.x += b1.x; a1.y += b1.y; a1.z += b1.z; a1.w += b1.w;
        }
        *(float4*)&S[kk * 68 + cq]     = a0;
        *(float4*)&S[kk * 68 + cq + 4] = a1;
    }
    __syncthreads();
    {
        int cc = t >> 2, kq = (t & 3) << 3;
        float v[8];
        #pragma unroll
        for (int i = 0; i < 8; ++i) v[i] = S[(kq + i) * 68 + cc];
        float* wt = g_WT + ((size_t)(b * C + cc)) * H + tk * 32 + kq;
        *(float4*)wt       = make_float4(v[0], v[1], v[2], v[3]);
        *(float4*)(wt + 4) = make_float4(v[4], v[5], v[6], v[7]);
    }
}

// ============ kctx: per (f,h): CTX[32b x 32i]
__global__ void __launch_bounds__(256) kctx(const float* __restrict__ Wi,
                                            const float* __restrict__ bi) {
    int f = blockIdx.x >> 3;
    int h = blockIdx.x & 7;
    int c = f * NH + h;
    int t = threadIdx.x;
    __shared__ __align__(16) float Vv[32 * 132];
    __shared__ __align__(16) float Wb[32 * 132];

    const float* Wv = Wi + (size_t)f * 3 * H * H + (size_t)2 * H * H + (size_t)(h * 32) * H;
    int bb = t & 31, w = t >> 5, ii0 = w * 4;
    ull acc[4] = {0ull, 0ull, 0ull, 0ull};

    for (int kc = 0; kc < H; kc += 128) {
        if (kc) __syncthreads();
        #pragma unroll
        for (int i = 0; i < 4; ++i) {
            int idx = t + (i << 8);
            int rr = idx >> 5, kq = (idx & 31) << 2;
            *(float4*)&Vv[rr * 132 + kq] = *(const float4*)(Wv + (size_t)rr * H + kc + kq);
            *(float4*)&Wb[rr * 132 + kq] = *(const float4*)(g_WT + ((size_t)(rr * C + c)) * H + kc + kq);
        }
        __syncthreads();
        #pragma unroll 8
        for (int kp = 0; kp < 64; ++kp) {
            ull x = *(const ull*)&Wb[bb * 132 + kp * 2];
            fma2(acc[0], x, *(const ull*)&Vv[(ii0 + 0) * 132 + kp * 2]);
            fma2(acc[1], x, *(const ull*)&Vv[(ii0 + 1) * 132 + kp * 2]);
            fma2(acc[2], x, *(const ull*)&Vv[(ii0 + 2) * 132 + kp * 2]);
            fma2(acc[3], x, *(const ull*)&Vv[(ii0 + 3) * 132 + kp * 2]);
        }
    }

    const float* bv = bi + f * 3 * H + 2 * H + h * 32;
    #pragma unroll
    for (int j = 0; j < 4; ++j) {
        float2 v = unpack2(acc[j]);
        g_ctx[((size_t)(f * B + bb)) * H + h * 32 + ii0 + j] = v.x + v.y + bv[ii0 + j];
    }
}

// ============ kho: 64 blocks (f, 32-wide i-tile): HO = CTX @ Wo^T + bo
__global__ void __launch_bounds__(256) kho(const float* __restrict__ Wo,
                                           const float* __restrict__ bo) {
    int f = blockIdx.x >> 3;
    int i0 = (blockIdx.x & 7) * 32;
    int t = threadIdx.x;
    __shared__ __align__(16) float Cs[32 * 260];
    __shared__ __align__(16) float Wos[32 * 36];

    #pragma unroll
    for (int i = 0; i < 8; ++i) {
        int idx = t + (i << 8);
        int rr = idx >> 6, jq = (idx & 63) << 2;
        *(float4*)&Cs[rr * 260 + jq] = *(const float4*)(g_ctx + ((size_t)(f * B + rr)) * H + jq);
    }

    int bb = t >> 3, ig = (t & 7) << 2;
    ull acc[2] = {0ull, 0ull};
    const float* Wof = Wo + (size_t)f * H * H;

    for (int jc = 0; jc < H; jc += 32) {
        __syncthreads();
        {
            int ii = t >> 3, jq = (t & 7) << 2;
            float4 v0 = *(const float4*)(Wof + (size_t)(i0 + ii) * H + jc + jq);
            Wos[(jq + 0) * 36 + ii] = v0.x;
            Wos[(jq + 1) * 36 + ii] = v0.y;
            Wos[(jq + 2) * 36 + ii] = v0.z;
            Wos[(jq + 3) * 36 + ii] = v0.w;
        }
        __syncthreads();
        #pragma unroll 8
        for (int jj = 0; jj < 32; ++jj) {
            float x = Cs[bb * 260 + jc + jj];
            ull xx = pack2(x, x);
            fma2(acc[0], xx, *(const ull*)&Wos[jj * 36 + ig]);
            fma2(acc[1], xx, *(const ull*)&Wos[jj * 36 + ig + 2]);
        }
    }

    const float* bof = bo + f * H + i0 + ig;
    float2 v0 = unpack2(acc[0]), v1 = unpack2(acc[1]);
    float* hp = g_ho + ((size_t)(f * B + bb)) * H + i0 + ig;
    *(float4*)hp = make_float4(v0.x + bof[0], v0.y + bof[1], v1.x + bof[2], v1.y + bof[3]);
}

// ============ k_meta: 64 blocks, 32-wide c-tiles: Y = X + X @ M
__global__ void __launch_bounds__(256) k_meta(const float* __restrict__ X,
                                              const float* __restrict__ M,
                                              float* __restrict__ Y) {
    int c0 = blockIdx.x * 32;
    int r0 = blockIdx.y * 32;
    __shared__ __align__(16) float Xs[32 * 36];
    __shared__ __align__(16) float Ms[32 * 36];
    int t = threadIdx.x;
    int r = t >> 3, cg = (t & 7) << 2;
    ull acc[2] = {0ull, 0ull};

    for (int kc = 0; kc < H; kc += 32) {
        if (kc) __syncthreads();
        {
            int rr = t >> 3, kk = (t & 7) << 2;
            *(float4*)&Xs[rr * 36 + kk] = *(const float4*)(X + (size_t)(r0 + rr) * H + kc + kk);
        }
        {
            int kk = t >> 3, cc = (t & 7) << 2;
            *(float4*)&Ms[kk * 36 + cc] = *(const float4*)(M + (size_t)(kc + kk) * H + c0 + cc);
        }
        __syncthreads();
        #pragma unroll
        for (int k = 0; k < 32; ++k) {
            float x = Xs[r * 36 + k];
            ull xx = pack2(x, x);
            fma2(acc[0], xx, *(const ull*)&Ms[k * 36 + cg]);
            fma2(acc[1], xx, *(const ull*)&Ms[k * 36 + cg + 2]);
        }
    }

    const float* xr = X + (size_t)(r0 + r) * H + c0 + cg;
    float4 a0 = *(const float4*)xr;
    float2 v0 = unpack2(acc[0]), v1 = unpack2(acc[1]);
    float* yr = Y + (size_t)(r0 + r) * H + c0 + cg;
    *(float4*)yr = make_float4(a0.x + v0.x, a0.y + v0.y, a0.z + v1.x, a0.w + v1.y);
}

// ============ K5b: strategy softmax + combine
__global__ void __launch_bounds__(256) k5b_out(const float* __restrict__ q,
                                               const float* __restrict__ sw,
                                               const float* __restrict__ sb,
                                               float* __restrict__ out) {
    int b = blockIdx.x;
    int t = threadIdx.x, lane = t & 31, w = t >> 5;
    __shared__ float qs[H];
    __shared__ float lg[F];
    __shared__ float pr[F];
    qs[t] = q[b * H + t];
    __syncthreads();
    {
        float s = 0.f;
        for (int j = lane; j < H; j += 32) s = fmaf(sw[(size_t)w * H + j], qs[j], s);
        #pragma unroll
        for (int o = 16; o; o >>= 1) s += __shfl_xor_sync(0xffffffffu, s, o);
        if (lane == 0) lg[w] = s + sb[w];
    }
    __syncthreads();
    if (t == 0) {
        float m = lg[0];
        #pragma unroll
        for (int f2 = 1; f2 < F; ++f2) m = fmaxf(m, lg[f2]);
        float sum = 0.f;
        #pragma unroll
        for (int f2 = 0; f2 < F; ++f2) { pr[f2] = __expf(lg[f2] - m); sum += pr[f2]; }
        float inv = 1.0f / sum;
        #pragma unroll
        for (int f2 = 0; f2 < F; ++f2) pr[f2] *= inv;
    }
    __syncthreads();
    float o = 0.f;
    #pragma unroll
    for (int f2 = 0; f2 < F; ++f2)
        o = fmaf(pr[f2], g_ho2[((size_t)(f2 * B + b)) * H + t], o);
    out[b * H + t] = o;
}

extern "C" void kernel_launch(void* const* d_in, const int* in_sizes, int n_in,
                              void* d_out, int out_size) {
    const float* q    = (const float*)d_in[0];
    const float* docs = (const float*)d_in[1];
    const float* cw   = (const float*)d_in[2];
    const float* Wi   = (const float*)d_in[4];
    const float* bi   = (const float*)d_in[5];
    const float* Wo   = (const float*)d_in[6];
    const float* bo   = (const float*)d_in[7];
    const float* sw   = (const float*)d_in[8];
    const float* sb   = (const float*)d_in[9];
    const float* M    = (const float*)d_in[10];
    float* out = (float*)d_out;

    float* ho;  cudaGetSymbolAddress((void**)&ho,  g_ho);
    float* ho2; cudaGetSymbolAddress((void**)&ho2, g_ho2);

    k1_prep<<<B * F, 256>>>(q, Wi, bi);
    k2_scores<<<dim3(NCHUNK, B), 128>>>(docs, cw);
    k4_wgemm<<<dim3(NSPLIT, B), 256>>>(docs, cw);
    kT_red<<<B * 8, 256>>>();                         // launch #4 -> profiled
    kctx<<<F * NH, 256>>>(Wi, bi);
    kho<<<F * 8, 256>>>(Wo, bo);
    k_meta<<<dim3(8, 8), 256>>>(ho,  M,                     ho2);
    k_meta<<<dim3(8, 8), 256>>>(ho2, M + (size_t)H * H,     ho);
    k_meta<<<dim3(8, 8), 256>>>(ho,  M + (size_t)2 * H * H, ho2);
    k5b_out<<<B, 256>>>(q, sw, sb, out);
}